// round 7
// baseline (speedup 1.0000x reference)
#include <cuda_runtime.h>

// Problem constants
#define BB 2
#define NN 2048
#define CC 1024
#define HH 16
#define HD 64
#define MROWS (BB*NN)        // 4096
#define SCALE 0.125f         // hd^-0.5
#define NEGINF (-1.0e30f)

typedef unsigned long long u64;

// ---- packed f32x2 helpers (sm_100+) ----
__device__ __forceinline__ u64 pk2(float lo, float hi) {
    u64 r; asm("mov.b64 %0, {%1, %2};" : "=l"(r) : "f"(lo), "f"(hi)); return r;
}
__device__ __forceinline__ void upk2(float& lo, float& hi, u64 v) {
    asm("mov.b64 {%0, %1}, %2;" : "=f"(lo), "=f"(hi) : "l"(v));
}
__device__ __forceinline__ void fma2(u64& d, u64 a, u64 b) {
    asm("fma.rn.f32x2 %0, %1, %2, %0;" : "+l"(d) : "l"(a), "l"(b));
}
__device__ __forceinline__ u64 mul2(u64 a, u64 b) {
    u64 r; asm("mul.rn.f32x2 %0, %1, %2;" : "=l"(r) : "l"(a), "l"(b)); return r;
}
__device__ __forceinline__ u64 f4lo(float4 f) { return pk2(f.x, f.y); }
__device__ __forceinline__ u64 f4hi(float4 f) { return pk2(f.z, f.w); }

// Scratch for projected+roped Q,K,V in [B,N,H*hd] layout (row = b*N+n, col = h*64+d)
__device__ float g_proj[3][(size_t)MROWS * CC];

// ---------------------------------------------------------------------------
// Kernel 1: fused projection  Y = X @ W^T + b, with RoPE epilogue for Q,K.
// 128x128 tile, BK=16, 256 threads, 8x8 per thread, f32x2 inner product.
// ---------------------------------------------------------------------------
__global__ __launch_bounds__(256, 2)
void proj_kernel(const float* __restrict__ q, const float* __restrict__ k, const float* __restrict__ v,
                 const float* __restrict__ Wq, const float* __restrict__ Wk, const float* __restrict__ Wv,
                 const float* __restrict__ bq, const float* __restrict__ bk, const float* __restrict__ bv,
                 const float* __restrict__ qcos, const float* __restrict__ qsin,
                 const float* __restrict__ kcos, const float* __restrict__ ksin)
{
    const int z = blockIdx.z;
    const float* X    = (z == 0) ? q  : (z == 1) ? k  : v;
    const float* W    = (z == 0) ? Wq : (z == 1) ? Wk : Wv;
    const float* bias = (z == 0) ? bq : (z == 1) ? bk : bv;
    const float* ct   = (z == 0) ? qcos : kcos;
    const float* st   = (z == 0) ? qsin : ksin;
    float* out = g_proj[z];

    __shared__ float As[16][128];   // [k][m] transposed
    __shared__ float Bs[16][128];   // [k][n] transposed

    const int tid = threadIdx.x;
    const int tx = tid & 15;
    const int ty = tid >> 4;
    const int row0 = blockIdx.y * 128;
    const int col0 = blockIdx.x * 128;

    int lr[2], lc[2];
    #pragma unroll
    for (int l = 0; l < 2; l++) {
        int f = tid + l * 256;
        lr[l] = f >> 2;
        lc[l] = (f & 3) << 2;
    }

    u64 acc2[8][4];
    #pragma unroll
    for (int i = 0; i < 8; i++)
        #pragma unroll
        for (int j = 0; j < 4; j++)
            acc2[i][j] = 0ull;

    float4 a_pf[2], b_pf[2];
    #pragma unroll
    for (int l = 0; l < 2; l++) {
        a_pf[l] = *(const float4*)&X[(size_t)(row0 + lr[l]) * CC + lc[l]];
        b_pf[l] = *(const float4*)&W[(size_t)(col0 + lr[l]) * CC + lc[l]];
    }

    for (int kt = 0; kt < CC; kt += 16) {
        __syncthreads();
        #pragma unroll
        for (int l = 0; l < 2; l++) {
            int r = lr[l], c4 = lc[l];
            As[c4 + 0][r] = a_pf[l].x; As[c4 + 1][r] = a_pf[l].y;
            As[c4 + 2][r] = a_pf[l].z; As[c4 + 3][r] = a_pf[l].w;
            Bs[c4 + 0][r] = b_pf[l].x; Bs[c4 + 1][r] = b_pf[l].y;
            Bs[c4 + 2][r] = b_pf[l].z; Bs[c4 + 3][r] = b_pf[l].w;
        }
        __syncthreads();

        if (kt + 16 < CC) {
            #pragma unroll
            for (int l = 0; l < 2; l++) {
                a_pf[l] = *(const float4*)&X[(size_t)(row0 + lr[l]) * CC + kt + 16 + lc[l]];
                b_pf[l] = *(const float4*)&W[(size_t)(col0 + lr[l]) * CC + kt + 16 + lc[l]];
            }
        }

        #pragma unroll
        for (int kk = 0; kk < 16; kk++) {
            float af[8];
            *(float4*)&af[0] = *(const float4*)&As[kk][ty * 8];
            *(float4*)&af[4] = *(const float4*)&As[kk][ty * 8 + 4];
            float4 bf0 = *(const float4*)&Bs[kk][tx * 8];
            float4 bf1 = *(const float4*)&Bs[kk][tx * 8 + 4];
            u64 b2[4] = {f4lo(bf0), f4hi(bf0), f4lo(bf1), f4hi(bf1)};
            #pragma unroll
            for (int i = 0; i < 8; i++) {
                u64 aa = pk2(af[i], af[i]);
                fma2(acc2[i][0], aa, b2[0]);
                fma2(acc2[i][1], aa, b2[1]);
                fma2(acc2[i][2], aa, b2[2]);
                fma2(acc2[i][3], aa, b2[3]);
            }
        }
    }

    const int cbase = col0 + tx * 8;
    const int jbase = (tx * 4) & 31;
    #pragma unroll
    for (int i = 0; i < 8; i++) {
        int r = row0 + ty * 8 + i;
        int n = r & (NN - 1);
        float vals[8];
        #pragma unroll
        for (int j4 = 0; j4 < 4; j4++)
            upk2(vals[2 * j4], vals[2 * j4 + 1], acc2[i][j4]);
        #pragma unroll
        for (int j = 0; j < 8; j++) vals[j] += bias[cbase + j];
        if (z < 2) {
            #pragma unroll
            for (int jp = 0; jp < 4; jp++) {
                int jj = jbase + jp;
                float c = ct[n * 32 + jj];
                float s = st[n * 32 + jj];
                float xr = vals[2 * jp], xi = vals[2 * jp + 1];
                vals[2 * jp]     = xr * c - xi * s;
                vals[2 * jp + 1] = xr * s + xi * c;
            }
        }
        *(float4*)&out[(size_t)r * CC + cbase]     = make_float4(vals[0], vals[1], vals[2], vals[3]);
        *(float4*)&out[(size_t)r * CC + cbase + 4] = make_float4(vals[4], vals[5], vals[6], vals[7]);
    }
}

// ---------------------------------------------------------------------------
// Kernel 2: flash attention v2. 128q x 64k tiles, 256 threads, 8x4 micro-tile.
// Row-pair-packed f32x2 accumulators; P stored transposed (k-major) with
// f4-rotation swizzle so PV loads P pairs directly. Dynamic smem 96KB.
// ---------------------------------------------------------------------------
__global__ __launch_bounds__(256, 2)
void attn_kernel(float* __restrict__ out)
{
    extern __shared__ float sm_[];
    float* qsT = sm_;               // [64 d][128 m], f4-rotated per d
    float* ksT = sm_ + 64 * 128;    // [64 d][64 k],  f4-rotated per d
    float* vsm = ksT + 64 * 64;     // [64 k][64 d],  natural
    float* Pt  = vsm + 64 * 64;     // [64 k][128 m], f4-rotated per k

    const int tid = threadIdx.x;
    const int tx = tid & 15;        // k-columns: 4*tx .. 4*tx+3
    const int ty = tid >> 4;        // q-rows:    8*ty .. 8*ty+7
    const int m0 = blockIdx.x * 128;
    const int b  = blockIdx.y >> 4;
    const int h  = blockIdx.y & 15;

    const float* Q = g_proj[0];
    const float* K = g_proj[1];
    const float* V = g_proj[2];
    const size_t headoff = (size_t)b * NN * CC + h * HD;

    // ---- load Q tile transposed+rotated: qsT[d][m] ----
    #pragma unroll
    for (int l = 0; l < 8; l++) {
        int f  = tid + l * 256;
        int r  = f >> 4;             // 0..127 (query row)
        int d4 = (f & 15) << 2;
        float4 a = *(const float4*)&Q[headoff + (size_t)(m0 + r) * CC + d4];
        float av[4] = {a.x, a.y, a.z, a.w};
        #pragma unroll
        for (int j = 0; j < 4; j++) {
            int d = d4 + j;
            int f4i = ((r >> 2) + d + (d >> 2)) & 31;
            qsT[d * 128 + 4 * f4i + (r & 3)] = av[j];
        }
    }

    // K/V per-thread load coords (64 rows x 64 d = 4 float4/thread)
    int lr[4], ld[4];
    #pragma unroll
    for (int l = 0; l < 4; l++) {
        int f = tid + l * 256;
        lr[l] = f >> 4;              // 0..63 (key row)
        ld[l] = (f & 15) << 2;
    }

    float m_i[8], l_i[8];
    u64 o2[4][4];                    // [row-pair p][col c], rows (8ty+2p, 8ty+2p+1)
    #pragma unroll
    for (int i = 0; i < 8; i++) { m_i[i] = NEGINF; l_i[i] = 0.f; }
    #pragma unroll
    for (int p = 0; p < 4; p++)
        #pragma unroll
        for (int c = 0; c < 4; c++) o2[p][c] = 0ull;

    // prefetch tile 0
    float4 k_pf[4], v_pf[4];
    #pragma unroll
    for (int l = 0; l < 4; l++) {
        k_pf[l] = *(const float4*)&K[headoff + (size_t)lr[l] * CC + ld[l]];
        v_pf[l] = *(const float4*)&V[headoff + (size_t)lr[l] * CC + ld[l]];
    }

    for (int t = 0; t < NN / 64; t++) {
        __syncthreads();   // prev PV reads of vsm/Pt done; Q store (t=0) ordered
        #pragma unroll
        for (int l = 0; l < 4; l++) {
            int r = lr[l], d4 = ld[l];
            float kv[4] = {k_pf[l].x, k_pf[l].y, k_pf[l].z, k_pf[l].w};
            #pragma unroll
            for (int j = 0; j < 4; j++) {
                int d = d4 + j;
                int f4i = ((r >> 2) + d + (d >> 2)) & 15;
                ksT[d * 64 + 4 * f4i + (r & 3)] = kv[j];
            }
            *(float4*)&vsm[r * 64 + d4] = v_pf[l];
        }
        __syncthreads();

        // prefetch next tile (overlaps all compute below)
        if (t + 1 < NN / 64) {
            const int kn1 = (t + 1) * 64;
            #pragma unroll
            for (int l = 0; l < 4; l++) {
                k_pf[l] = *(const float4*)&K[headoff + (size_t)(kn1 + lr[l]) * CC + ld[l]];
                v_pf[l] = *(const float4*)&V[headoff + (size_t)(kn1 + lr[l]) * CC + ld[l]];
            }
        }

        // ---- S = Q K^T : 8 rows x 4 cols per thread, row-pair packed ----
        u64 s2[4][4];
        #pragma unroll
        for (int p = 0; p < 4; p++)
            #pragma unroll
            for (int c = 0; c < 4; c++) s2[p][c] = 0ull;

        #pragma unroll 4
        for (int d = 0; d < 64; d++) {
            int rq = d + (d >> 2);
            float4 qa = *(const float4*)&qsT[d * 128 + 4 * ((2 * ty + rq) & 31)];     // rows 8ty..+3
            float4 qb = *(const float4*)&qsT[d * 128 + 4 * ((2 * ty + 1 + rq) & 31)]; // rows 8ty+4..+7
            float4 kf = *(const float4*)&ksT[d * 64 + 4 * ((tx + rq) & 15)];          // cols 4tx..+3
            u64 qp0 = f4lo(qa), qp1 = f4hi(qa), qp2 = f4lo(qb), qp3 = f4hi(qb);
            u64 c0 = pk2(kf.x, kf.x), c1 = pk2(kf.y, kf.y);
            u64 c2 = pk2(kf.z, kf.z), c3 = pk2(kf.w, kf.w);
            fma2(s2[0][0], qp0, c0); fma2(s2[0][1], qp0, c1); fma2(s2[0][2], qp0, c2); fma2(s2[0][3], qp0, c3);
            fma2(s2[1][0], qp1, c0); fma2(s2[1][1], qp1, c1); fma2(s2[1][2], qp1, c2); fma2(s2[1][3], qp1, c3);
            fma2(s2[2][0], qp2, c0); fma2(s2[2][1], qp2, c1); fma2(s2[2][2], qp2, c2); fma2(s2[2][3], qp2, c3);
            fma2(s2[3][0], qp3, c0); fma2(s2[3][1], qp3, c1); fma2(s2[3][2], qp3, c2); fma2(s2[3][3], qp3, c3);
        }

        // ---- online softmax over 8 rows (reduction across tx = 16 lanes) ----
        float s[8][4];
        #pragma unroll
        for (int p = 0; p < 4; p++)
            #pragma unroll
            for (int c = 0; c < 4; c++)
                upk2(s[2 * p][c], s[2 * p + 1][c], s2[p][c]);

        float a8[8];
        #pragma unroll
        for (int i = 0; i < 8; i++) {
            float rm = NEGINF;
            #pragma unroll
            for (int j = 0; j < 4; j++) { s[i][j] *= SCALE; rm = fmaxf(rm, s[i][j]); }
            #pragma unroll
            for (int off = 8; off > 0; off >>= 1)
                rm = fmaxf(rm, __shfl_xor_sync(0xffffffffu, rm, off));
            float mnew = fmaxf(m_i[i], rm);
            a8[i] = __expf(m_i[i] - mnew);
            float rs = 0.f;
            #pragma unroll
            for (int j = 0; j < 4; j++) { float p_ = __expf(s[i][j] - mnew); s[i][j] = p_; rs += p_; }
            #pragma unroll
            for (int off = 8; off > 0; off >>= 1)
                rs += __shfl_xor_sync(0xffffffffu, rs, off);
            l_i[i] = l_i[i] * a8[i] + rs;
            m_i[i] = mnew;
        }
        #pragma unroll
        for (int p = 0; p < 4; p++) {
            u64 al = pk2(a8[2 * p], a8[2 * p + 1]);
            #pragma unroll
            for (int c = 0; c < 4; c++) o2[p][c] = mul2(o2[p][c], al);
        }

        // ---- store P transposed (k-major) with rotation ----
        #pragma unroll
        for (int c = 0; c < 4; c++) {
            int kcol = 4 * tx + c;
            int rp = kcol + (kcol >> 2);
            float4 lo = make_float4(s[0][c], s[1][c], s[2][c], s[3][c]);   // m4 = 2ty
            float4 hi = make_float4(s[4][c], s[5][c], s[6][c], s[7][c]);   // m4 = 2ty+1
            *(float4*)&Pt[kcol * 128 + 4 * ((2 * ty + rp) & 31)]     = lo;
            *(float4*)&Pt[kcol * 128 + 4 * ((2 * ty + 1 + rp) & 31)] = hi;
        }
        __syncthreads();

        // ---- O += P V : pairs load pre-packed from Pt ----
        #pragma unroll 4
        for (int k = 0; k < 64; k++) {
            int rp = k + (k >> 2);
            float4 pa = *(const float4*)&Pt[k * 128 + 4 * ((2 * ty + rp) & 31)];
            float4 pb = *(const float4*)&Pt[k * 128 + 4 * ((2 * ty + 1 + rp) & 31)];
            float4 vf = *(const float4*)&vsm[k * 64 + 4 * tx];
            u64 pp0 = f4lo(pa), pp1 = f4hi(pa), pp2 = f4lo(pb), pp3 = f4hi(pb);
            u64 b0 = pk2(vf.x, vf.x), b1 = pk2(vf.y, vf.y);
            u64 b2 = pk2(vf.z, vf.z), b3 = pk2(vf.w, vf.w);
            fma2(o2[0][0], pp0, b0); fma2(o2[0][1], pp0, b1); fma2(o2[0][2], pp0, b2); fma2(o2[0][3], pp0, b3);
            fma2(o2[1][0], pp1, b0); fma2(o2[1][1], pp1, b1); fma2(o2[1][2], pp1, b2); fma2(o2[1][3], pp1, b3);
            fma2(o2[2][0], pp2, b0); fma2(o2[2][1], pp2, b1); fma2(o2[2][2], pp2, b2); fma2(o2[2][3], pp2, b3);
            fma2(o2[3][0], pp3, b0); fma2(o2[3][1], pp3, b1); fma2(o2[3][2], pp3, b2); fma2(o2[3][3], pp3, b3);
        }
    }

    // ---- finalize: O /= l, write [B,N,H*hd] ----
    float ofin[8][4];
    #pragma unroll
    for (int p = 0; p < 4; p++) {
        u64 iv = pk2(1.0f / l_i[2 * p], 1.0f / l_i[2 * p + 1]);
        #pragma unroll
        for (int c = 0; c < 4; c++) {
            u64 r = mul2(o2[p][c], iv);
            upk2(ofin[2 * p][c], ofin[2 * p + 1][c], r);
        }
    }
    #pragma unroll
    for (int i = 0; i < 8; i++) {
        *(float4*)&out[headoff + (size_t)(m0 + 8 * ty + i) * CC + 4 * tx] =
            make_float4(ofin[i][0], ofin[i][1], ofin[i][2], ofin[i][3]);
    }
}

#define SMEM_ATTN ((64*128 + 64*64 + 64*64 + 64*128) * 4)   // 96 KB

// ---------------------------------------------------------------------------
// Inputs (metadata order): q,k,v,q_cos,q_sin,k_cos,k_sin,Wq,bq,Wk,bk,Wv,bv
// ---------------------------------------------------------------------------
extern "C" void kernel_launch(void* const* d_in, const int* in_sizes, int n_in,
                              void* d_out, int out_size)
{
    (void)in_sizes; (void)n_in; (void)out_size;
    const float* q    = (const float*)d_in[0];
    const float* k    = (const float*)d_in[1];
    const float* v    = (const float*)d_in[2];
    const float* qcos = (const float*)d_in[3];
    const float* qsin = (const float*)d_in[4];
    const float* kcos = (const float*)d_in[5];
    const float* ksin = (const float*)d_in[6];
    const float* Wq   = (const float*)d_in[7];
    const float* bq   = (const float*)d_in[8];
    const float* Wk   = (const float*)d_in[9];
    const float* bk   = (const float*)d_in[10];
    const float* Wv   = (const float*)d_in[11];
    const float* bv   = (const float*)d_in[12];
    float* out = (float*)d_out;

    cudaFuncSetAttribute(attn_kernel, cudaFuncAttributeMaxDynamicSharedMemorySize, SMEM_ATTN);

    dim3 gp(CC / 128, MROWS / 128, 3);      // (8, 32, 3)
    proj_kernel<<<gp, 256>>>(q, k, v, Wq, Wk, Wv, bq, bk, bv, qcos, qsin, kcos, ksin);

    dim3 ga(NN / 128, BB * HH);             // (16, 32)
    attn_kernel<<<ga, 256, SMEM_ATTN>>>(out);
}